// round 15
// baseline (speedup 1.0000x reference)
#include <cuda_runtime.h>
#include <cuda_bf16.h>

// Problem constants (fixed by setup_inputs)
#define BB 32      // batch
#define TT 2048    // timesteps
#define HH 512     // hidden per direction
#define DH 1024    // D*H
#define CC 1024    // input feature size
#define NWARP 64   // fused-pass warps per batch
#define WT (TT / NWARP)  // 32 timesteps per warp
#define NPART 16   // merged partials per batch (one per block)
#define SSTAGES 3  // smem ring stages per warp (1 timestep = 4KB each)
#define PRE 2      // stages kept in flight
#define KSPLIT 4   // qproj K-split (k-slice of 256 per block)
#define PFT 8      // timesteps L2-prefetched per warp during qproj window

typedef unsigned long long u64;

// ---------------- scratch (no runtime allocation allowed) ----------------
__device__ float g_qpart[KSPLIT][BB * DH];         // split-K query partials
__device__ float g_scores[BB * TT];                // raw (pre-softmax) scores
__device__ float g_pm[BB * NPART];                 // per-block running max
__device__ float g_pl[BB * NPART];                 // per-block running sum
__device__ float g_pa[(size_t)BB * NPART * DH];    // per-block weighted accum (2 MB)

// packed f32x2 fma helpers (Blackwell FFMA2 — PTX-only)
__device__ __forceinline__ void ffma2(u64& d, u64 a, u64 b) {
  asm("fma.rn.f32x2 %0, %1, %2, %0;" : "+l"(d) : "l"(a), "l"(b));
}
__device__ __forceinline__ float2 u2f(u64 v) {
  float2 f;
  asm("mov.b64 {%0, %1}, %2;" : "=f"(f.x), "=f"(f.y) : "l"(v));
  return f;
}
// PDL: block until the upstream grid in the same stream has completed.
__device__ __forceinline__ void grid_dep_wait() {
  asm volatile("griddepcontrol.wait;" ::: "memory");
}

// ---------------------------------------------------------------------------
// Kernel A (best measured): smem-tiled, internally pipelined query projection
// with f32x2 math. grid (32 d-tiles, KSPLIT=4) x 256 thr, 64 KB smem in 4
// quarter-stages, all cp.async'd up front. Warp computes 4 d's x 32 b.
// ---------------------------------------------------------------------------
__global__ __launch_bounds__(256, 2) void qproj_kernel(
    const float* __restrict__ input, const float* __restrict__ Wq) {
  const int tid = threadIdx.x;
  const int warp = tid >> 5;
  const int lane = tid & 31;            // lane = b
  const int dt = blockIdx.x;            // d-tile (32 d's)
  const int ks = blockIdx.y;            // k-slice (256 k's)
  const int kbase = ks * (CC / KSPLIT);

  // smem: quarter q at smq + q*1024: [0,512) sIn (kc16 x b32), [512,1024) sW
  extern __shared__ float4 smq[];

  // prologue: stage ALL four quarters, one commit group each
#pragma unroll
  for (int qq = 0; qq < 4; ++qq) {
    float4* sInQ = smq + qq * 1024;
    float4* sWQ = sInQ + 512;
    const int kq = kbase + qq * 64;  // quarter covers k in [kq, kq+64)
#pragma unroll
    for (int i = 0; i < 2; ++i) {
      const int idx = i * 256 + tid;   // (b, kc), kc fast (16 per b)
      const int b = idx >> 4, kc = idx & 15;
      const float* src = input + (size_t)b * CC + kq + kc * 4;
      unsigned dst = (unsigned)__cvta_generic_to_shared(sInQ + kc * 32 + b);
      asm volatile("cp.async.cg.shared.global [%0], [%1], 16;" ::"r"(dst),
                   "l"(src));
    }
#pragma unroll
    for (int i = 0; i < 2; ++i) {
      const int idx = i * 256 + tid;   // (dl, kc), kc fast (16 per dl)
      const int dl = idx >> 4, kc = idx & 15;
      const float* src = Wq + (size_t)(dt * 32 + dl) * CC + kq + kc * 4;
      unsigned dst = (unsigned)__cvta_generic_to_shared(sWQ + dl * 16 + kc);
      asm volatile("cp.async.cg.shared.global [%0], [%1], 16;" ::"r"(dst),
                   "l"(src));
    }
    asm volatile("cp.async.commit_group;");
  }

  // accumulators: 4 d's, each 4 floats as 2 x f32x2
  u64 a0x = 0, a0y = 0, a1x = 0, a1y = 0;
  u64 a2x = 0, a2y = 0, a3x = 0, a3y = 0;

#pragma unroll
  for (int qq = 0; qq < 4; ++qq) {
    if (qq == 0) asm volatile("cp.async.wait_group 3;");
    if (qq == 1) asm volatile("cp.async.wait_group 2;");
    if (qq == 2) asm volatile("cp.async.wait_group 1;");
    if (qq == 3) asm volatile("cp.async.wait_group 0;");
    __syncthreads();

    const float4* sInQ = smq + qq * 1024;
    const float4* wrow = sInQ + 512 + warp * 4 * 16;

#pragma unroll
    for (int kc = 0; kc < 16; ++kc) {
      const ulonglong2 in2 = *(const ulonglong2*)(sInQ + kc * 32 + lane);
      const ulonglong2 w0 = *(const ulonglong2*)(wrow + kc);
      const ulonglong2 w1 = *(const ulonglong2*)(wrow + 16 + kc);
      const ulonglong2 w2 = *(const ulonglong2*)(wrow + 32 + kc);
      const ulonglong2 w3 = *(const ulonglong2*)(wrow + 48 + kc);
      ffma2(a0x, w0.x, in2.x); ffma2(a0y, w0.y, in2.y);
      ffma2(a1x, w1.x, in2.x); ffma2(a1y, w1.y, in2.y);
      ffma2(a2x, w2.x, in2.x); ffma2(a2y, w2.y, in2.y);
      ffma2(a3x, w3.x, in2.x); ffma2(a3y, w3.y, in2.y);
    }
  }

  const float2 f0a = u2f(a0x), f0b = u2f(a0y);
  const float2 f1a = u2f(a1x), f1b = u2f(a1y);
  const float2 f2a = u2f(a2x), f2b = u2f(a2y);
  const float2 f3a = u2f(a3x), f3b = u2f(a3y);
  float4 q;
  q.x = (f0a.x + f0a.y) + (f0b.x + f0b.y);
  q.y = (f1a.x + f1a.y) + (f1b.x + f1b.y);
  q.z = (f2a.x + f2a.y) + (f2b.x + f2b.y);
  q.w = (f3a.x + f3a.y) + (f3b.x + f3b.y);
  *(float4*)(&g_qpart[ks][lane * DH + dt * 32 + warp * 4]) = q;
}

// ---------------------------------------------------------------------------
// Kernel B: warp-autonomous fused scores + online softmax, cp.async pipeline,
// block-level partial merge. PDL: launches while qproj runs, issues its key
// prologue + L2 PREFETCH of timesteps PRE..PRE+PFT-1 (using qproj's idle
// DRAM window), then griddepcontrol.wait before consuming g_qpart.
// grid (NWARP/4=16, BB)=512 blocks, 48 KB smem -> single wave.
// enc_h layout (D, T, B, H): keys[b,t,dir*H+h] = enc_h[((dir*T+t)*B+b)*H+h]
// ---------------------------------------------------------------------------
__global__ __launch_bounds__(128, 4) void attn_main_kernel(
    const float* __restrict__ enc_h, const float* __restrict__ bq) {
  const int b = blockIdx.y;
  const int warp = threadIdx.x >> 5;
  const int lane = threadIdx.x & 31;
  const int widx = blockIdx.x * 4 + warp;   // 0..NWARP-1 within this batch
  const int t0 = widx * WT;

  const float scale = 0.04419417382415922f;  // 1/sqrt(512)

  extern __shared__ float4 ring[];           // [4 warps][SSTAGES][256] = 48KB
  float4* ringw = ring + warp * (SSTAGES * 256);

  const size_t tstride = (size_t)BB * HH;          // floats per timestep
  const size_t dirstride = (size_t)TT * BB * HH;   // floats per direction
  const float* base0 = enc_h + ((size_t)t0 * BB + b) * HH + lane * 4;
  const float* base1 = base0 + dirstride;

#define LOAD_STAGE(T, SLOT)                                                  \
  {                                                                          \
    const float* r0_ = base0 + (size_t)(T)*tstride;                          \
    const float* r1_ = base1 + (size_t)(T)*tstride;                          \
    float4* d_ = ringw + (SLOT)*256 + lane;                                  \
    _Pragma("unroll") for (int p = 0; p < 4; ++p) {                          \
      unsigned sa_ = (unsigned)__cvta_generic_to_shared(d_ + p * 32);        \
      asm volatile("cp.async.cg.shared.global [%0], [%1], 16;" ::"r"(sa_),   \
                   "l"(r0_ + p * 128));                                      \
    }                                                                        \
    _Pragma("unroll") for (int p = 0; p < 4; ++p) {                          \
      unsigned sa_ = (unsigned)__cvta_generic_to_shared(d_ + 128 + p * 32);  \
      asm volatile("cp.async.cg.shared.global [%0], [%1], 16;" ::"r"(sa_),   \
                   "l"(r1_ + p * 128));                                      \
    }                                                                        \
    asm volatile("cp.async.commit_group;");                                  \
  }

  // prologue FIRST: independent of qproj — overlaps it under PDL
  LOAD_STAGE(0, 0)
  LOAD_STAGE(1, 1)

  // L2 prefetch of timesteps PRE..PRE+PFT-1 (4 KB per t per warp; one 128B
  // line per lane per t: lanes 0-15 cover dir0, lanes 16-31 cover dir1).
  // Runs in qproj's DRAM-idle window; main loop's early cp.asyncs hit L2.
  {
    const float* row0 = enc_h + ((size_t)t0 * BB + b) * HH;  // no lane offset
    const float* rowd = row0 + (lane < 16 ? 0 : dirstride) + (lane & 15) * 32;
#pragma unroll
    for (int t = PRE; t < PRE + PFT; ++t) {
      const float* pf = rowd + (size_t)t * tstride;
      asm volatile("prefetch.global.L2 [%0];" ::"l"(pf));
    }
  }

  // wait for qproj grid completion before consuming its output
  grid_dep_wait();

  // q for this lane: q[p] covers d = p*128 + lane*4
  float4 q[8];
#pragma unroll
  for (int p = 0; p < 8; ++p) {
    const int d = p * 128 + lane * 4;
    const float4 bb = *(const float4*)(bq + d);
    float4 acc = bb;
#pragma unroll
    for (int ks = 0; ks < KSPLIT; ++ks) {
      const float4 pp = *(const float4*)(&g_qpart[ks][b * DH + d]);
      acc.x += pp.x; acc.y += pp.y; acc.z += pp.z; acc.w += pp.w;
    }
    q[p] = acc;
  }

  float4 a[8];
#pragma unroll
  for (int p = 0; p < 8; ++p) a[p] = make_float4(0.f, 0.f, 0.f, 0.f);
  float m = -1e30f, l = 0.f;

#pragma unroll
  for (int i = 0; i < WT; ++i) {
    // exact-count waits: only real groups are committed
    if (i + PRE < WT) {
      LOAD_STAGE(i + PRE, (i + PRE) % SSTAGES)
      asm volatile("cp.async.wait_group 2;");   // stage i complete
    } else if (i == WT - 2) {
      asm volatile("cp.async.wait_group 1;");   // one group (stage WT-1) left
    } else {                                    // i == WT-1
      asm volatile("cp.async.wait_group 0;");
    }

    const float4* kp = ringw + (i % SSTAGES) * 256 + lane;
    float4 k[8];
#pragma unroll
    for (int p = 0; p < 8; ++p) k[p] = kp[p * 32];

    float s = 0.f;
#pragma unroll
    for (int p = 0; p < 8; ++p)
      s += q[p].x * k[p].x + q[p].y * k[p].y + q[p].z * k[p].z +
           q[p].w * k[p].w;
#pragma unroll
    for (int off = 16; off >= 1; off >>= 1)
      s += __shfl_xor_sync(0xffffffffu, s, off);
    s *= scale;

    if (lane == 0) g_scores[b * TT + t0 + i] = s;

    if (s > m) {  // warp-uniform branch (s identical on all lanes)
      const float r = __expf(m - s);
#pragma unroll
      for (int p = 0; p < 8; ++p) {
        a[p].x *= r; a[p].y *= r; a[p].z *= r; a[p].w *= r;
      }
      l *= r;
      m = s;
    }
    const float w = __expf(s - m);
    l += w;
#pragma unroll
    for (int p = 0; p < 8; ++p) {
      a[p].x += w * k[p].x;
      a[p].y += w * k[p].y;
      a[p].z += w * k[p].z;
      a[p].w += w * k[p].w;
    }
  }
#undef LOAD_STAGE

  // ---- block-level merge of the 4 warps' partials (reuse ring smem) ----
  __shared__ float s_m[4], s_l[4];
  if (lane == 0) { s_m[warp] = m; s_l[warp] = l; }
  __syncthreads();

  const float Mb = fmaxf(fmaxf(s_m[0], s_m[1]), fmaxf(s_m[2], s_m[3]));
  const float Lb = s_l[0] * __expf(s_m[0] - Mb) + s_l[1] * __expf(s_m[1] - Mb) +
                   s_l[2] * __expf(s_m[2] - Mb) + s_l[3] * __expf(s_m[3] - Mb);
  const float wf = __expf(m - Mb);  // warp-uniform rescale factor

  // scaled a -> smem: ring[warp*256 + p*32 + lane] covers d = p*128+lane*4
  float4* mw = ring + warp * 256;
#pragma unroll
  for (int p = 0; p < 8; ++p) {
    float4 v = a[p];
    v.x *= wf; v.y *= wf; v.z *= wf; v.w *= wf;
    mw[p * 32 + lane] = v;
  }
  __syncthreads();

  // cooperative sum of 4 warps' vectors -> one partial per block
  float4* pa4 = (float4*)(g_pa + (size_t)(b * NPART + blockIdx.x) * DH);
#pragma unroll
  for (int r = 0; r < 2; ++r) {
    const int idx = r * 128 + threadIdx.x;  // 0..255 float4s
    const float4 v0 = ring[idx];
    const float4 v1 = ring[256 + idx];
    const float4 v2 = ring[512 + idx];
    const float4 v3 = ring[768 + idx];
    float4 v;
    v.x = v0.x + v1.x + v2.x + v3.x;
    v.y = v0.y + v1.y + v2.y + v3.y;
    v.z = v0.z + v1.z + v2.z + v3.z;
    v.w = v0.w + v1.w + v2.w + v3.w;
    pa4[idx] = v;
  }
  if (threadIdx.x == 0) {
    g_pm[b * NPART + blockIdx.x] = Mb;
    g_pl[b * NPART + blockIdx.x] = Lb;
  }
}

// ---------------------------------------------------------------------------
// Kernel C: combine per-block partials -> attn_values + normalized scores.
// PDL: launches during attn_main, waits at entry (ramp overlapped).
// grid (BB, 8), 128 threads: block handles 128 d's + 256 score elements.
// ---------------------------------------------------------------------------
__global__ __launch_bounds__(128) void combine_kernel(float* __restrict__ out) {
  grid_dep_wait();   // attn_main grid complete; its writes visible

  const int b = blockIdx.x;
  const int ds = blockIdx.y;
  const int j = threadIdx.x;

  __shared__ float sm[NPART], sw[NPART];
  __shared__ float sL;
  if (j < NPART) sm[j] = g_pm[b * NPART + j];
  __syncthreads();

  float M = -1e30f;
#pragma unroll
  for (int w = 0; w < NPART; ++w) M = fmaxf(M, sm[w]);
  if (j < NPART) sw[j] = __expf(sm[j] - M);
  __syncthreads();

  if (j == 0) {
    float L = 0.f;
#pragma unroll
    for (int w = 0; w < NPART; ++w) L += g_pl[b * NPART + w] * sw[w];
    sL = 1.f / L;
  }
  __syncthreads();
  const float invL = sL;

  const int d = ds * 128 + j;
  const float* pa = g_pa + (size_t)b * NPART * DH + d;
  float v0 = 0.f, v1 = 0.f, v2 = 0.f, v3 = 0.f;
#pragma unroll
  for (int w = 0; w < NPART; w += 4) {
    v0 += sw[w + 0] * pa[(size_t)(w + 0) * DH];
    v1 += sw[w + 1] * pa[(size_t)(w + 1) * DH];
    v2 += sw[w + 2] * pa[(size_t)(w + 2) * DH];
    v3 += sw[w + 3] * pa[(size_t)(w + 3) * DH];
  }
  out[b * DH + d] = (v0 + v1 + v2 + v3) * invL;

  // fused scores normalization: this block covers t in [ds*256, ds*256+256)
  const int tb = ds * 256 + j * 2;
  const float2 s2 = *(const float2*)(g_scores + b * TT + tb);
  float2 o2;
  o2.x = __expf(s2.x - M) * invL;
  o2.y = __expf(s2.y - M) * invL;
  *(float2*)(out + BB * DH + b * TT + tb) = o2;
}

// ---------------------------------------------------------------------------
extern "C" void kernel_launch(void* const* d_in, const int* in_sizes, int n_in,
                              void* d_out, int out_size) {
  const float* input = (const float*)d_in[0];   // (32, 1024)
  const float* enc_h = (const float*)d_in[1];   // (2, 2048, 32, 512)
  // d_in[2] decoder_state: unused
  const float* Wq = (const float*)d_in[3];      // (1024, 1024)
  const float* bq = (const float*)d_in[4];      // (1024,)
  // d_in[5] t: unused
  float* out = (float*)d_out;  // [attn_values (32*1024)] ++ [attn_scores (32*2048)]

  const int smem_main = 4 * SSTAGES * 256 * sizeof(float4);  // 48 KB
  const int smem_qp = 4096 * sizeof(float4);                 // 64 KB
  cudaFuncSetAttribute(attn_main_kernel,
                       cudaFuncAttributeMaxDynamicSharedMemorySize, smem_main);
  cudaFuncSetAttribute(qproj_kernel,
                       cudaFuncAttributeMaxDynamicSharedMemorySize, smem_qp);

  qproj_kernel<<<dim3(32, KSPLIT), 256, smem_qp>>>(input, Wq);

  // attn_main with PDL (falls back to a plain launch on error)
  {
    cudaLaunchConfig_t cfg = {};
    cfg.gridDim = dim3(NWARP / 4, BB);
    cfg.blockDim = dim3(128, 1, 1);
    cfg.dynamicSmemBytes = smem_main;
    cfg.stream = 0;
    cudaLaunchAttribute at[1];
    at[0].id = cudaLaunchAttributeProgrammaticStreamSerialization;
    at[0].val.programmaticStreamSerializationAllowed = 1;
    cfg.attrs = at;
    cfg.numAttrs = 1;
    if (cudaLaunchKernelEx(&cfg, attn_main_kernel, enc_h, bq) != cudaSuccess)
      attn_main_kernel<<<dim3(NWARP / 4, BB), 128, smem_main>>>(enc_h, bq);
  }

  // combine with PDL (falls back to a plain launch on error)
  {
    cudaLaunchConfig_t cfg = {};
    cfg.gridDim = dim3(BB, 8);
    cfg.blockDim = dim3(128, 1, 1);
    cfg.dynamicSmemBytes = 0;
    cfg.stream = 0;
    cudaLaunchAttribute at[1];
    at[0].id = cudaLaunchAttributeProgrammaticStreamSerialization;
    at[0].val.programmaticStreamSerializationAllowed = 1;
    cfg.attrs = at;
    cfg.numAttrs = 1;
    if (cudaLaunchKernelEx(&cfg, combine_kernel, out) != cudaSuccess)
      combine_kernel<<<dim3(BB, 8), 128>>>(out);
  }
}

// round 16
// speedup vs baseline: 1.1027x; 1.1027x over previous
#include <cuda_runtime.h>
#include <cuda_bf16.h>

// Problem constants (fixed by setup_inputs)
#define BB 32      // batch
#define TT 2048    // timesteps
#define HH 512     // hidden per direction
#define DH 1024    // D*H
#define CC 1024    // input feature size
#define NWARP 64   // fused-pass warps per batch
#define WT (TT / NWARP)  // 32 timesteps per warp
#define NPART 16   // merged partials per batch (one per block)
#define SSTAGES 3  // smem ring stages per warp (1 timestep = 4KB each)
#define PRE 2      // stages kept in flight
#define KSPLIT 4   // qproj K-split (k-slice of 256 per block)

typedef unsigned long long u64;

// ---------------- scratch (no runtime allocation allowed) ----------------
__device__ float g_qpart[KSPLIT][BB * DH];         // split-K query partials
__device__ float g_scores[BB * TT];                // raw (pre-softmax) scores
__device__ float g_pm[BB * NPART];                 // per-block running max
__device__ float g_pl[BB * NPART];                 // per-block running sum
__device__ float g_pa[(size_t)BB * NPART * DH];    // per-block weighted accum (2 MB)

// packed f32x2 fma helpers (Blackwell FFMA2 — PTX-only)
__device__ __forceinline__ void ffma2(u64& d, u64 a, u64 b) {
  asm("fma.rn.f32x2 %0, %1, %2, %0;" : "+l"(d) : "l"(a), "l"(b));
}
__device__ __forceinline__ float2 u2f(u64 v) {
  float2 f;
  asm("mov.b64 {%0, %1}, %2;" : "=f"(f.x), "=f"(f.y) : "l"(v));
  return f;
}
// PDL: block until the upstream grid in the same stream has completed.
__device__ __forceinline__ void grid_dep_wait() {
  asm volatile("griddepcontrol.wait;" ::: "memory");
}

// ---------------------------------------------------------------------------
// Kernel A (best measured): smem-tiled, internally pipelined query projection
// with f32x2 math. grid (32 d-tiles, KSPLIT=4) x 256 thr, 64 KB smem in 4
// quarter-stages, all cp.async'd up front. Warp computes 4 d's x 32 b.
// ---------------------------------------------------------------------------
__global__ __launch_bounds__(256, 2) void qproj_kernel(
    const float* __restrict__ input, const float* __restrict__ Wq) {
  const int tid = threadIdx.x;
  const int warp = tid >> 5;
  const int lane = tid & 31;            // lane = b
  const int dt = blockIdx.x;            // d-tile (32 d's)
  const int ks = blockIdx.y;            // k-slice (256 k's)
  const int kbase = ks * (CC / KSPLIT);

  // smem: quarter q at smq + q*1024: [0,512) sIn (kc16 x b32), [512,1024) sW
  extern __shared__ float4 smq[];

  // prologue: stage ALL four quarters, one commit group each
#pragma unroll
  for (int qq = 0; qq < 4; ++qq) {
    float4* sInQ = smq + qq * 1024;
    float4* sWQ = sInQ + 512;
    const int kq = kbase + qq * 64;  // quarter covers k in [kq, kq+64)
#pragma unroll
    for (int i = 0; i < 2; ++i) {
      const int idx = i * 256 + tid;   // (b, kc), kc fast (16 per b)
      const int b = idx >> 4, kc = idx & 15;
      const float* src = input + (size_t)b * CC + kq + kc * 4;
      unsigned dst = (unsigned)__cvta_generic_to_shared(sInQ + kc * 32 + b);
      asm volatile("cp.async.cg.shared.global [%0], [%1], 16;" ::"r"(dst),
                   "l"(src));
    }
#pragma unroll
    for (int i = 0; i < 2; ++i) {
      const int idx = i * 256 + tid;   // (dl, kc), kc fast (16 per dl)
      const int dl = idx >> 4, kc = idx & 15;
      const float* src = Wq + (size_t)(dt * 32 + dl) * CC + kq + kc * 4;
      unsigned dst = (unsigned)__cvta_generic_to_shared(sWQ + dl * 16 + kc);
      asm volatile("cp.async.cg.shared.global [%0], [%1], 16;" ::"r"(dst),
                   "l"(src));
    }
    asm volatile("cp.async.commit_group;");
  }

  // accumulators: 4 d's, each 4 floats as 2 x f32x2
  u64 a0x = 0, a0y = 0, a1x = 0, a1y = 0;
  u64 a2x = 0, a2y = 0, a3x = 0, a3y = 0;

#pragma unroll
  for (int qq = 0; qq < 4; ++qq) {
    if (qq == 0) asm volatile("cp.async.wait_group 3;");
    if (qq == 1) asm volatile("cp.async.wait_group 2;");
    if (qq == 2) asm volatile("cp.async.wait_group 1;");
    if (qq == 3) asm volatile("cp.async.wait_group 0;");
    __syncthreads();

    const float4* sInQ = smq + qq * 1024;
    const float4* wrow = sInQ + 512 + warp * 4 * 16;

#pragma unroll
    for (int kc = 0; kc < 16; ++kc) {
      const ulonglong2 in2 = *(const ulonglong2*)(sInQ + kc * 32 + lane);
      const ulonglong2 w0 = *(const ulonglong2*)(wrow + kc);
      const ulonglong2 w1 = *(const ulonglong2*)(wrow + 16 + kc);
      const ulonglong2 w2 = *(const ulonglong2*)(wrow + 32 + kc);
      const ulonglong2 w3 = *(const ulonglong2*)(wrow + 48 + kc);
      ffma2(a0x, w0.x, in2.x); ffma2(a0y, w0.y, in2.y);
      ffma2(a1x, w1.x, in2.x); ffma2(a1y, w1.y, in2.y);
      ffma2(a2x, w2.x, in2.x); ffma2(a2y, w2.y, in2.y);
      ffma2(a3x, w3.x, in2.x); ffma2(a3y, w3.y, in2.y);
    }
  }

  const float2 f0a = u2f(a0x), f0b = u2f(a0y);
  const float2 f1a = u2f(a1x), f1b = u2f(a1y);
  const float2 f2a = u2f(a2x), f2b = u2f(a2y);
  const float2 f3a = u2f(a3x), f3b = u2f(a3y);
  float4 q;
  q.x = (f0a.x + f0a.y) + (f0b.x + f0b.y);
  q.y = (f1a.x + f1a.y) + (f1b.x + f1b.y);
  q.z = (f2a.x + f2a.y) + (f2b.x + f2b.y);
  q.w = (f3a.x + f3a.y) + (f3b.x + f3b.y);
  *(float4*)(&g_qpart[ks][lane * DH + dt * 32 + warp * 4]) = q;
}

// ---------------------------------------------------------------------------
// Kernel B: fused scores + online softmax; keys move via cp.async.bulk (TMA
// bulk copy, 2 x 2KB contiguous rows per warp-stage) completing on per-warp
// mbarriers — bypasses the per-thread LDGSTS/L1tex path entirely.
// smem: [0,96) per-warp mbarriers (4x3), ring at byte 1024 (48 KB).
// grid (NWARP/4=16, BB)=512 blocks, 128 thr -> 4 blocks/SM, single wave.
// PDL: key prologue issued before griddepcontrol.wait (overlaps qproj).
// enc_h layout (D, T, B, H): keys[b,t,dir*H+h] = enc_h[((dir*T+t)*B+b)*H+h]
// ---------------------------------------------------------------------------
__global__ __launch_bounds__(128, 4) void attn_main_kernel(
    const float* __restrict__ enc_h, const float* __restrict__ bq) {
  const int b = blockIdx.y;
  const int warp = threadIdx.x >> 5;
  const int lane = threadIdx.x & 31;
  const int widx = blockIdx.x * 4 + warp;   // 0..NWARP-1 within this batch
  const int t0 = widx * WT;

  const float scale = 0.04419417382415922f;  // 1/sqrt(512)

  extern __shared__ char smem_raw[];
  const unsigned sb = (unsigned)__cvta_generic_to_shared(smem_raw);
  const unsigned mbar = sb + warp * 24;              // 3 mbarriers (8B each)
  float4* ring = (float4*)(smem_raw + 1024);         // 4 warps x 3 x 256 f4
  float4* ringw = ring + warp * (SSTAGES * 256);
  const unsigned ringw_b = sb + 1024 + warp * (SSTAGES * 4096);

  // init per-warp mbarriers (count=1: one arrive.expect_tx per phase)
  if (lane == 0) {
#pragma unroll
    for (int s = 0; s < SSTAGES; ++s)
      asm volatile("mbarrier.init.shared.b64 [%0], 1;" ::"r"(mbar + s * 8)
                   : "memory");
  }
  __syncwarp();
  asm volatile("fence.proxy.async.shared::cta;" ::: "memory");

  const size_t tstride = (size_t)BB * HH;          // floats per timestep
  const size_t dirstride = (size_t)TT * BB * HH;   // floats per direction
  const float* row0 = enc_h + ((size_t)t0 * BB + b) * HH;  // 2KB-aligned rows
  const float* row1 = row0 + dirstride;

#define PRODUCE(T)                                                           \
  {                                                                          \
    const int slot_ = (T) % SSTAGES;                                         \
    if (lane == 0) {                                                         \
      asm volatile(                                                          \
          "mbarrier.arrive.expect_tx.shared.b64 _, [%0], 4096;" ::"r"(       \
              mbar + slot_ * 8)                                              \
          : "memory");                                                       \
      asm volatile(                                                          \
          "cp.async.bulk.shared::cluster.global.mbarrier::complete_tx::"     \
          "bytes [%0], [%1], 2048, [%2];" ::"r"(ringw_b + slot_ * 4096),     \
          "l"(row0 + (size_t)(T)*tstride), "r"(mbar + slot_ * 8)             \
          : "memory");                                                       \
      asm volatile(                                                          \
          "cp.async.bulk.shared::cluster.global.mbarrier::complete_tx::"     \
          "bytes [%0], [%1], 2048, [%2];" ::"r"(ringw_b + slot_ * 4096 +     \
                                                2048),                       \
          "l"(row1 + (size_t)(T)*tstride), "r"(mbar + slot_ * 8)             \
          : "memory");                                                       \
    }                                                                        \
  }

#define MWAIT(SLOT, PH)                                                      \
  asm volatile(                                                              \
      "{\n.reg .pred P;\n"                                                   \
      "MW%=: mbarrier.try_wait.parity.acquire.cta.shared::cta.b64 P, [%0], " \
      "%1;\n"                                                                \
      "@!P bra MW%=;\n}" ::"r"(mbar + (SLOT)*8), "r"((unsigned)(PH))         \
      : "memory")

  // prologue FIRST: independent of qproj — overlaps it under PDL
  PRODUCE(0)
  PRODUCE(1)

  // wait for qproj grid completion before consuming its output
  grid_dep_wait();

  // q for this lane: q[p] covers d = p*128 + lane*4
  float4 q[8];
#pragma unroll
  for (int p = 0; p < 8; ++p) {
    const int d = p * 128 + lane * 4;
    const float4 bb = *(const float4*)(bq + d);
    float4 acc = bb;
#pragma unroll
    for (int ks = 0; ks < KSPLIT; ++ks) {
      const float4 pp = *(const float4*)(&g_qpart[ks][b * DH + d]);
      acc.x += pp.x; acc.y += pp.y; acc.z += pp.z; acc.w += pp.w;
    }
    q[p] = acc;
  }

  float4 a[8];
#pragma unroll
  for (int p = 0; p < 8; ++p) a[p] = make_float4(0.f, 0.f, 0.f, 0.f);
  float m = -1e30f, l = 0.f;

#pragma unroll
  for (int i = 0; i < WT; ++i) {
    // wait for stage i (slot i%3, phase (i/3)&1)
    MWAIT(i % SSTAGES, (i / SSTAGES) & 1);

    // load keys to registers, then syncwarp BEFORE re-arming this ring area
    const float4* kp = ringw + (i % SSTAGES) * 256 + lane;
    float4 k[8];
#pragma unroll
    for (int p = 0; p < 8; ++p) k[p] = kp[p * 32];
    __syncwarp();

    if (i + PRE < WT) PRODUCE(i + PRE)

    float s = 0.f;
#pragma unroll
    for (int p = 0; p < 8; ++p)
      s += q[p].x * k[p].x + q[p].y * k[p].y + q[p].z * k[p].z +
           q[p].w * k[p].w;
#pragma unroll
    for (int off = 16; off >= 1; off >>= 1)
      s += __shfl_xor_sync(0xffffffffu, s, off);
    s *= scale;

    if (lane == 0) g_scores[b * TT + t0 + i] = s;

    if (s > m) {  // warp-uniform branch (s identical on all lanes)
      const float r = __expf(m - s);
#pragma unroll
      for (int p = 0; p < 8; ++p) {
        a[p].x *= r; a[p].y *= r; a[p].z *= r; a[p].w *= r;
      }
      l *= r;
      m = s;
    }
    const float w = __expf(s - m);
    l += w;
#pragma unroll
    for (int p = 0; p < 8; ++p) {
      a[p].x += w * k[p].x;
      a[p].y += w * k[p].y;
      a[p].z += w * k[p].z;
      a[p].w += w * k[p].w;
    }
  }
#undef PRODUCE
#undef MWAIT

  // ---- block-level merge of the 4 warps' partials (reuse ring smem) ----
  __shared__ float s_m[4], s_l[4];
  if (lane == 0) { s_m[warp] = m; s_l[warp] = l; }
  __syncthreads();   // also: all warps done with their ring slots

  const float Mb = fmaxf(fmaxf(s_m[0], s_m[1]), fmaxf(s_m[2], s_m[3]));
  const float Lb = s_l[0] * __expf(s_m[0] - Mb) + s_l[1] * __expf(s_m[1] - Mb) +
                   s_l[2] * __expf(s_m[2] - Mb) + s_l[3] * __expf(s_m[3] - Mb);
  const float wf = __expf(m - Mb);  // warp-uniform rescale factor

  // scaled a -> smem: ring[warp*256 + p*32 + lane] covers d = p*128+lane*4
  float4* mw = ring + warp * 256;
#pragma unroll
  for (int p = 0; p < 8; ++p) {
    float4 v = a[p];
    v.x *= wf; v.y *= wf; v.z *= wf; v.w *= wf;
    mw[p * 32 + lane] = v;
  }
  __syncthreads();

  // cooperative sum of 4 warps' vectors -> one partial per block
  float4* pa4 = (float4*)(g_pa + (size_t)(b * NPART + blockIdx.x) * DH);
#pragma unroll
  for (int r = 0; r < 2; ++r) {
    const int idx = r * 128 + threadIdx.x;  // 0..255 float4s
    const float4 v0 = ring[idx];
    const float4 v1 = ring[256 + idx];
    const float4 v2 = ring[512 + idx];
    const float4 v3 = ring[768 + idx];
    float4 v;
    v.x = v0.x + v1.x + v2.x + v3.x;
    v.y = v0.y + v1.y + v2.y + v3.y;
    v.z = v0.z + v1.z + v2.z + v3.z;
    v.w = v0.w + v1.w + v2.w + v3.w;
    pa4[idx] = v;
  }
  if (threadIdx.x == 0) {
    g_pm[b * NPART + blockIdx.x] = Mb;
    g_pl[b * NPART + blockIdx.x] = Lb;
  }
}

// ---------------------------------------------------------------------------
// Kernel C: combine per-block partials -> attn_values + normalized scores.
// PDL: launches during attn_main, waits at entry (ramp overlapped).
// grid (BB, 8), 128 threads: block handles 128 d's + 256 score elements.
// ---------------------------------------------------------------------------
__global__ __launch_bounds__(128) void combine_kernel(float* __restrict__ out) {
  grid_dep_wait();   // attn_main grid complete; its writes visible

  const int b = blockIdx.x;
  const int ds = blockIdx.y;
  const int j = threadIdx.x;

  __shared__ float sm[NPART], sw[NPART];
  __shared__ float sL;
  if (j < NPART) sm[j] = g_pm[b * NPART + j];
  __syncthreads();

  float M = -1e30f;
#pragma unroll
  for (int w = 0; w < NPART; ++w) M = fmaxf(M, sm[w]);
  if (j < NPART) sw[j] = __expf(sm[j] - M);
  __syncthreads();

  if (j == 0) {
    float L = 0.f;
#pragma unroll
    for (int w = 0; w < NPART; ++w) L += g_pl[b * NPART + w] * sw[w];
    sL = 1.f / L;
  }
  __syncthreads();
  const float invL = sL;

  const int d = ds * 128 + j;
  const float* pa = g_pa + (size_t)b * NPART * DH + d;
  float v0 = 0.f, v1 = 0.f, v2 = 0.f, v3 = 0.f;
#pragma unroll
  for (int w = 0; w < NPART; w += 4) {
    v0 += sw[w + 0] * pa[(size_t)(w + 0) * DH];
    v1 += sw[w + 1] * pa[(size_t)(w + 1) * DH];
    v2 += sw[w + 2] * pa[(size_t)(w + 2) * DH];
    v3 += sw[w + 3] * pa[(size_t)(w + 3) * DH];
  }
  out[b * DH + d] = (v0 + v1 + v2 + v3) * invL;

  // fused scores normalization: this block covers t in [ds*256, ds*256+256)
  const int tb = ds * 256 + j * 2;
  const float2 s2 = *(const float2*)(g_scores + b * TT + tb);
  float2 o2;
  o2.x = __expf(s2.x - M) * invL;
  o2.y = __expf(s2.y - M) * invL;
  *(float2*)(out + BB * DH + b * TT + tb) = o2;
}

// ---------------------------------------------------------------------------
extern "C" void kernel_launch(void* const* d_in, const int* in_sizes, int n_in,
                              void* d_out, int out_size) {
  const float* input = (const float*)d_in[0];   // (32, 1024)
  const float* enc_h = (const float*)d_in[1];   // (2, 2048, 32, 512)
  // d_in[2] decoder_state: unused
  const float* Wq = (const float*)d_in[3];      // (1024, 1024)
  const float* bq = (const float*)d_in[4];      // (1024,)
  // d_in[5] t: unused
  float* out = (float*)d_out;  // [attn_values (32*1024)] ++ [attn_scores (32*2048)]

  const int smem_main = 1024 + 4 * SSTAGES * 4096;  // mbarriers + 48 KB ring
  const int smem_qp = 4096 * sizeof(float4);        // 64 KB
  cudaFuncSetAttribute(attn_main_kernel,
                       cudaFuncAttributeMaxDynamicSharedMemorySize, smem_main);
  cudaFuncSetAttribute(qproj_kernel,
                       cudaFuncAttributeMaxDynamicSharedMemorySize, smem_qp);

  qproj_kernel<<<dim3(32, KSPLIT), 256, smem_qp>>>(input, Wq);

  // attn_main with PDL (falls back to a plain launch on error)
  {
    cudaLaunchConfig_t cfg = {};
    cfg.gridDim = dim3(NWARP / 4, BB);
    cfg.blockDim = dim3(128, 1, 1);
    cfg.dynamicSmemBytes = smem_main;
    cfg.stream = 0;
    cudaLaunchAttribute at[1];
    at[0].id = cudaLaunchAttributeProgrammaticStreamSerialization;
    at[0].val.programmaticStreamSerializationAllowed = 1;
    cfg.attrs = at;
    cfg.numAttrs = 1;
    if (cudaLaunchKernelEx(&cfg, attn_main_kernel, enc_h, bq) != cudaSuccess)
      attn_main_kernel<<<dim3(NWARP / 4, BB), 128, smem_main>>>(enc_h, bq);
  }

  // combine with PDL (falls back to a plain launch on error)
  {
    cudaLaunchConfig_t cfg = {};
    cfg.gridDim = dim3(BB, 8);
    cfg.blockDim = dim3(128, 1, 1);
    cfg.dynamicSmemBytes = 0;
    cfg.stream = 0;
    cudaLaunchAttribute at[1];
    at[0].id = cudaLaunchAttributeProgrammaticStreamSerialization;
    at[0].val.programmaticStreamSerializationAllowed = 1;
    cfg.attrs = at;
    cfg.numAttrs = 1;
    if (cudaLaunchKernelEx(&cfg, combine_kernel, out) != cudaSuccess)
      combine_kernel<<<dim3(BB, 8), 128>>>(out);
  }
}